// round 1
// baseline (speedup 1.0000x reference)
#include <cuda_runtime.h>

#define HID   256
#define TLEN  128
#define INCH  1024
#define CTXD  16

// shared memory layout (floats)
#define HSM_FLOATS   33024          // 256*128 h + padding for benign OOB reads
#define WSU_FLOATS   9216           // weight-stage / scratch union (36 KB)
#define SMEM_FLOATS  (HSM_FLOATS + WSU_FLOATS + TLEN + 64)

__device__ __forceinline__ void load8(float r[8], const float* p) {
    float4 a = *(const float4*)(p);
    float4 b = *(const float4*)(p + 4);
    r[0]=a.x; r[1]=a.y; r[2]=a.z; r[3]=a.w;
    r[4]=b.x; r[5]=b.y; r[6]=b.z; r[7]=b.w;
}
__device__ __forceinline__ void store8(float* p, const float r[8]) {
    *(float4*)(p)     = make_float4(r[0], r[1], r[2], r[3]);
    *(float4*)(p + 4) = make_float4(r[4], r[5], r[6], r[7]);
}

// One dilated conv layer: y = conv(h, w, dil=D, pad_right=D); leaky; +skip; unit-norm cols.
// Thread (mg,ng) owns out rows [o0,o0+8) x cols [t0,t0+8). Accumulators in registers.
template<int D>
__device__ __forceinline__ void conv_layer(
    float* __restrict__ hsm, float* __restrict__ wsu, float* __restrict__ colfac,
    const float* __restrict__ cw, const float* __restrict__ cb,
    int tid, int mg, int ng, int t0, int o0)
{
    float acc[8][8];
    #pragma unroll
    for (int m = 0; m < 8; m++)
        #pragma unroll
        for (int j = 0; j < 8; j++) acc[m][j] = 0.f;

    const int o = tid >> 1, prt = tid & 1;

    for (int kc = 0; kc < 16; kc++) {
        __syncthreads();   // previous chunk's weight reads done
        // stage weights: ws[o][36] (rows padded 32->36 floats to kill bank conflicts)
        {
            const float4* src = (const float4*)(cw + o * (HID * 2) + kc * 32 + prt * 16);
            float4* dst = (float4*)(wsu + o * 36 + prt * 16);
            dst[0] = src[0]; dst[1] = src[1]; dst[2] = src[2]; dst[3] = src[3];
        }
        __syncthreads();

        #pragma unroll 4
        for (int i = 0; i < 16; i++) {
            const float* hrow = hsm + (kc * 16 + i) * TLEN;
            float h1[8], h2[8];
            load8(h1, hrow + t0);               // tap 0: h[i, t]
            if constexpr (D < 8) {
                // tap 1 via register shift of [t0..t0+15]; zero-select at right edge
                float hn[8];
                load8(hn, hrow + t0 + 8);       // may read past row end for ng=15: padded + masked
                #pragma unroll
                for (int j = 0; j < 8; j++) {
                    float v = (D + j < 8) ? h1[D + j] : hn[D + j - 8];
                    h2[j] = (t0 + D + j < TLEN) ? v : 0.f;
                }
            } else {
                // D multiple of 8: the whole 8-col group is either fully valid or fully zero
                const bool valid = (t0 + D) < TLEN;
                float tmp[8];
                load8(tmp, hrow + t0 + (valid ? D : 0));
                #pragma unroll
                for (int j = 0; j < 8; j++) h2[j] = valid ? tmp[j] : 0.f;
            }
            const float* wr = wsu + o0 * 36 + i * 2;
            #pragma unroll
            for (int m = 0; m < 8; m++) {
                float2 w = *(const float2*)(wr + m * 36);
                #pragma unroll
                for (int j = 0; j < 8; j++) acc[m][j] = fmaf(w.x, h1[j], acc[m][j]);
                #pragma unroll
                for (int j = 0; j < 8; j++) acc[m][j] = fmaf(w.y, h2[j], acc[m][j]);
            }
        }
    }
    __syncthreads();   // all weight reads done before wsu is reused as scratch

    // epilogue: bias + leaky relu + skip + partial column sums of squares
    float psum[8];
    #pragma unroll
    for (int j = 0; j < 8; j++) psum[j] = 0.f;
    #pragma unroll
    for (int m = 0; m < 8; m++) {
        float bb = cb[o0 + m];
        float sk[8];
        load8(sk, hsm + (o0 + m) * TLEN + t0);
        #pragma unroll
        for (int j = 0; j < 8; j++) {
            float y = acc[m][j] + bb;
            y = (y > 0.f) ? y : 0.2f * y;
            y += sk[j];
            acc[m][j] = y;
            psum[j] = fmaf(y, y, psum[j]);
        }
    }
    store8(wsu + mg * TLEN + t0, psum);     // scratch[32][128]
    __syncthreads();
    if (tid < TLEN) {
        float s = 0.f;
        #pragma unroll
        for (int g = 0; g < 32; g++) s += wsu[g * TLEN + tid];
        colfac[tid] = 1.0f / (sqrtf(s) + 1e-8f);
    }
    __syncthreads();
    float fac[8];
    load8(fac, colfac + t0);
    #pragma unroll
    for (int m = 0; m < 8; m++) {
        #pragma unroll
        for (int j = 0; j < 8; j++) acc[m][j] *= fac[j];
        store8(hsm + (o0 + m) * TLEN + t0, acc[m]);
    }
    __syncthreads();
}

__global__ __launch_bounds__(512, 1)
void Model_26147760898465_kernel(
    const float* __restrict__ x,
    const float* __restrict__ proj_w, const float* __restrict__ proj_b,
    const float* __restrict__ conv_w, const float* __restrict__ conv_b,
    const float* __restrict__ ev_w,  const float* __restrict__ ev_b,
    const float* __restrict__ sw_w,  const float* __restrict__ sw_b,
    float* __restrict__ out)
{
    extern __shared__ float sm[];
    float* hsm    = sm;
    float* wsu    = sm + HSM_FLOATS;
    float* colfac = wsu + WSU_FLOATS;
    float* redv   = colfac + TLEN;
    int*   redi   = (int*)(redv + 32);

    const int tid = threadIdx.x;
    const int b   = blockIdx.x;
    const int mg  = tid >> 4, ng = tid & 15;
    const int t0  = ng * 8,   o0 = mg * 8;

    // ---------------- 1x1 projection: h = proj_w @ x[b] + proj_b ----------------
    {
        float acc[8][8];
        #pragma unroll
        for (int m = 0; m < 8; m++)
            #pragma unroll
            for (int j = 0; j < 8; j++) acc[m][j] = 0.f;

        const float* xb  = x + (size_t)b * INCH * TLEN;
        float* xs  = wsu;            // [16][128]
        float* pws = wsu + 2048;     // [256][20] padded
        const int o = tid >> 1, prt = tid & 1;

        for (int kc = 0; kc < 64; kc++) {
            __syncthreads();
            ((float4*)xs)[tid] = ((const float4*)(xb + kc * 16 * TLEN))[tid];
            {
                const float4* src = (const float4*)(proj_w + o * INCH + kc * 16 + prt * 8);
                float4* dst = (float4*)(pws + o * 20 + prt * 8);
                dst[0] = src[0]; dst[1] = src[1];
            }
            __syncthreads();

            #pragma unroll 4
            for (int i = 0; i < 16; i++) {
                float hv[8];
                load8(hv, xs + i * TLEN + t0);
                const float* wr = pws + o0 * 20 + i;
                #pragma unroll
                for (int m = 0; m < 8; m++) {
                    float w = wr[m * 20];
                    #pragma unroll
                    for (int j = 0; j < 8; j++) acc[m][j] = fmaf(w, hv[j], acc[m][j]);
                }
            }
        }
        __syncthreads();
        #pragma unroll
        for (int m = 0; m < 8; m++) {
            float bb = proj_b[o0 + m];
            #pragma unroll
            for (int j = 0; j < 8; j++) acc[m][j] += bb;
            store8(hsm + (o0 + m) * TLEN + t0, acc[m]);
        }
        __syncthreads();
    }

    // ---------------- dilated conv stack (DILATIONS = 1,2,4,8,16,32,64,1) ----------------
    conv_layer<1 >(hsm, wsu, colfac, conv_w + 0 * HID * HID * 2, conv_b + 0 * HID, tid, mg, ng, t0, o0);
    conv_layer<2 >(hsm, wsu, colfac, conv_w + 1 * HID * HID * 2, conv_b + 1 * HID, tid, mg, ng, t0, o0);
    conv_layer<4 >(hsm, wsu, colfac, conv_w + 2 * HID * HID * 2, conv_b + 2 * HID, tid, mg, ng, t0, o0);
    conv_layer<8 >(hsm, wsu, colfac, conv_w + 3 * HID * HID * 2, conv_b + 3 * HID, tid, mg, ng, t0, o0);
    conv_layer<16>(hsm, wsu, colfac, conv_w + 4 * HID * HID * 2, conv_b + 4 * HID, tid, mg, ng, t0, o0);
    conv_layer<32>(hsm, wsu, colfac, conv_w + 5 * HID * HID * 2, conv_b + 5 * HID, tid, mg, ng, t0, o0);
    conv_layer<64>(hsm, wsu, colfac, conv_w + 6 * HID * HID * 2, conv_b + 6 * HID, tid, mg, ng, t0, o0);
    conv_layer<1 >(hsm, wsu, colfac, conv_w + 7 * HID * HID * 2, conv_b + 7 * HID, tid, mg, ng, t0, o0);

    // ---------------- heads: event vectors, switch, top-1, outputs ----------------
    {
        // stage ev_w [16*256] and sw_w [256] into smem
        {
            float4* dst = (float4*)wsu;
            const float4* esrc = (const float4*)ev_w;
            dst[tid]       = esrc[tid];
            dst[tid + 512] = esrc[tid + 512];
            if (tid < 64) ((float4*)(wsu + 4096))[tid] = ((const float4*)sw_w)[tid];
        }
        __syncthreads();
        float* evs = wsu + 4096 + 256;   // [16][128]

        if (tid < TLEN) {
            float a[CTXD + 1];
            #pragma unroll
            for (int c = 0; c < CTXD; c++) a[c] = ev_b[c];
            a[CTXD] = sw_b[0];
            for (int i = 0; i < HID; i++) {
                float hv = hsm[i * TLEN + tid];
                #pragma unroll
                for (int c = 0; c < CTXD; c++) a[c] = fmaf(wsu[c * HID + i], hv, a[c]);
                a[CTXD] = fmaf(wsu[4096 + i], hv, a[CTXD]);
            }
            #pragma unroll
            for (int c = 0; c < CTXD; c++) evs[c * TLEN + tid] = a[c];
            colfac[tid] = fmaxf(a[CTXD], 0.f);   // attn = relu(switch)
        }
        __syncthreads();

        // top-1 over t with lowest-index tie-break (matches jax top_k)
        if (tid < TLEN) {
            float v = colfac[tid]; int idx = tid;
            #pragma unroll
            for (int off = 16; off > 0; off >>= 1) {
                float ov = __shfl_down_sync(0xffffffff, v, off);
                int   oi = __shfl_down_sync(0xffffffff, idx, off);
                if (ov > v || (ov == v && oi < idx)) { v = ov; idx = oi; }
            }
            if ((tid & 31) == 0) { redv[tid >> 5] = v; redi[tid >> 5] = idx; }
        }
        __syncthreads();
        if (tid == 0) {
            float v = redv[0]; int idx = redi[0];
            #pragma unroll
            for (int w = 1; w < 4; w++)
                if (redv[w] > v || (redv[w] == v && redi[w] < idx)) { v = redv[w]; idx = redi[w]; }
            redv[0] = v; redi[0] = idx;
        }
        __syncthreads();

        const int   bi = redi[0];
        const float bv = redv[0];
        // output: [vecs (B*CTX) | scheduling (B*T)]
        if (tid < CTXD) out[(size_t)b * CTXD + tid] = evs[tid * TLEN + bi];
        if (tid < TLEN) out[(size_t)gridDim.x * CTXD + (size_t)b * TLEN + tid] = (tid == bi) ? bv : 0.f;
    }
}

extern "C" void kernel_launch(void* const* d_in, const int* in_sizes, int n_in,
                              void* d_out, int out_size)
{
    const float* x      = (const float*)d_in[0];
    const float* proj_w = (const float*)d_in[1];
    const float* proj_b = (const float*)d_in[2];
    const float* conv_w = (const float*)d_in[3];
    const float* conv_b = (const float*)d_in[4];
    const float* ev_w   = (const float*)d_in[5];
    const float* ev_b   = (const float*)d_in[6];
    const float* sw_w   = (const float*)d_in[7];
    const float* sw_b   = (const float*)d_in[8];
    float* out = (float*)d_out;

    const int B = in_sizes[0] / (INCH * TLEN);   // 256
    const size_t smem = SMEM_FLOATS * sizeof(float);   // ~166 KB
    cudaFuncSetAttribute(Model_26147760898465_kernel,
                         cudaFuncAttributeMaxDynamicSharedMemorySize, (int)smem);
    Model_26147760898465_kernel<<<B, 512, smem>>>(
        x, proj_w, proj_b, conv_w, conv_b, ev_w, ev_b, sw_w, sw_b, out);
}